// round 1
// baseline (speedup 1.0000x reference)
#include <cuda_runtime.h>

// LIF spike recurrence over the last (time) axis.
//   u = TAU*u*(1-o_prev) + x_t;  o = (u > VTH) ? 1 : 0
// x: [16,128,512,32] fp32 -> 1,048,576 neurons x 32 contiguous timesteps.
//
// Strategy: HBM-streaming problem (268 MB total). Use smem transpose so all
// global traffic is coalesced float4; each thread owns one neuron's 32-step
// serial recurrence, read/written from a padded smem row (stride 9 float4 ->
// conflict-free LDS.128/STS.128).

#define TAU 0.25f
#define VTH 0.5f

#define THREADS 256
#define F4_PER_NEURON 8          // 32 timesteps / 4
#define PAD_STRIDE 9             // 8 + 1 float4 pad -> conflict-free
#define F4_PER_TILE (THREADS * F4_PER_NEURON)  // 2048 float4 per block

__global__ __launch_bounds__(THREADS)
void lif_kernel(const float4* __restrict__ x, float4* __restrict__ out) {
    __shared__ float4 tile[THREADS * PAD_STRIDE];  // 36 KB

    const int t = threadIdx.x;
    const size_t base = (size_t)blockIdx.x * F4_PER_TILE;

    // Phase 1: coalesced global -> smem (transposed into padded rows)
    #pragma unroll
    for (int i = 0; i < F4_PER_NEURON; i++) {
        int g = t + i * THREADS;       // float4 index within the tile
        int n = g >> 3;                // neuron within tile
        int j = g & 7;                 // float4 within neuron row
        tile[n * PAD_STRIDE + j] = x[base + g];
    }
    __syncthreads();

    // Phase 2: per-thread serial recurrence over own smem row.
    // Process 4 timesteps per float4 chunk; write spikes back in place.
    float u = 0.0f, o = 0.0f;
    #pragma unroll
    for (int j = 0; j < F4_PER_NEURON; j++) {
        float4 f = tile[t * PAD_STRIDE + j];

        u = TAU * u * (1.0f - o) + f.x;
        o = (u > VTH) ? 1.0f : 0.0f;
        f.x = o;

        u = TAU * u * (1.0f - o) + f.y;
        o = (u > VTH) ? 1.0f : 0.0f;
        f.y = o;

        u = TAU * u * (1.0f - o) + f.z;
        o = (u > VTH) ? 1.0f : 0.0f;
        f.z = o;

        u = TAU * u * (1.0f - o) + f.w;
        o = (u > VTH) ? 1.0f : 0.0f;
        f.w = o;

        tile[t * PAD_STRIDE + j] = f;
    }
    __syncthreads();

    // Phase 3: coalesced smem -> global
    #pragma unroll
    for (int i = 0; i < F4_PER_NEURON; i++) {
        int g = t + i * THREADS;
        int n = g >> 3;
        int j = g & 7;
        out[base + g] = tile[n * PAD_STRIDE + j];
    }
}

extern "C" void kernel_launch(void* const* d_in, const int* in_sizes, int n_in,
                              void* d_out, int out_size) {
    const float4* x = (const float4*)d_in[0];
    float4* o = (float4*)d_out;

    // in_sizes[0] = 16*128*512*32 = 33,554,432 floats
    long long n_floats = in_sizes[0];
    long long neurons = n_floats / 32;
    int blocks = (int)(neurons / THREADS);   // 4096 for the given shape

    lif_kernel<<<blocks, THREADS>>>(x, o);
}

// round 2
// speedup vs baseline: 1.0445x; 1.0445x over previous
#include <cuda_runtime.h>

// LIF spike recurrence over the last (time) axis.
//   u = TAU*u*(1-o_prev) + x_t;  o = (u > VTH) ? 1 : 0
// x: [16,128,512,32] fp32 -> 1,048,576 neurons x 32 contiguous timesteps.
//
// Round 2: warp-autonomous tiles. With thread t owning neuron t, warp w's
// coalesced float4 range [w*256,(w+1)*256) covers exactly warp w's own 32
// neurons -> the smem transpose never crosses warps. __syncwarp only, XOR
// swizzle (no pad, 32KB/block), 7 blocks/SM, streaming cache hints.

#define TAU 0.25f
#define VTH 0.5f

#define THREADS 256
#define F4_PER_WARP 256           // 32 neurons * 8 float4
#define F4_PER_TILE (THREADS * 8) // 2048 float4 per block

__global__ __launch_bounds__(THREADS, 7)
void lif_kernel(const float4* __restrict__ x, float4* __restrict__ out) {
    __shared__ float4 tile[F4_PER_TILE];  // 32 KB, xor-swizzled rows

    const int lane = threadIdx.x & 31;
    const int warp = threadIdx.x >> 5;
    float4* wtile = tile + warp * F4_PER_WARP;
    const size_t wbase = (size_t)blockIdx.x * F4_PER_TILE + (size_t)warp * F4_PER_WARP;

    // Phase 1: coalesced global -> warp-local smem (swizzled).
    // g = i*32+lane => j = g&7 , n = g>>3 ; 8-lane STS.128 phase: same n,
    // distinct j -> distinct (j ^ (n&7)) -> conflict-free.
    #pragma unroll
    for (int i = 0; i < 8; i++) {
        int g = i * 32 + lane;
        int n = g >> 3;
        int j = g & 7;
        wtile[(n << 3) | (j ^ (n & 7))] = __ldcs(&x[wbase + g]);
    }
    __syncwarp();

    // Phase 2: per-lane serial recurrence over own swizzled smem row.
    // LDS.128 phase (8 lanes): distinct n&7 -> distinct bank-quads.
    {
        const int n = lane;
        float u = 0.0f, o = 0.0f;
        #pragma unroll
        for (int j = 0; j < 8; j++) {
            const int idx = (n << 3) | (j ^ (n & 7));
            float4 f = wtile[idx];

            u = TAU * u * (1.0f - o) + f.x;
            o = (u > VTH) ? 1.0f : 0.0f;
            f.x = o;

            u = TAU * u * (1.0f - o) + f.y;
            o = (u > VTH) ? 1.0f : 0.0f;
            f.y = o;

            u = TAU * u * (1.0f - o) + f.z;
            o = (u > VTH) ? 1.0f : 0.0f;
            f.z = o;

            u = TAU * u * (1.0f - o) + f.w;
            o = (u > VTH) ? 1.0f : 0.0f;
            f.w = o;

            wtile[idx] = f;
        }
    }
    __syncwarp();

    // Phase 3: warp-local smem -> coalesced global.
    #pragma unroll
    for (int i = 0; i < 8; i++) {
        int g = i * 32 + lane;
        int n = g >> 3;
        int j = g & 7;
        __stcs(&out[wbase + g], wtile[(n << 3) | (j ^ (n & 7))]);
    }
}

extern "C" void kernel_launch(void* const* d_in, const int* in_sizes, int n_in,
                              void* d_out, int out_size) {
    const float4* x = (const float4*)d_in[0];
    float4* o = (float4*)d_out;

    long long n_floats = in_sizes[0];          // 33,554,432
    long long neurons = n_floats / 32;         // 1,048,576
    int blocks = (int)(neurons / THREADS);     // 4096

    lif_kernel<<<blocks, THREADS>>>(x, o);
}

// round 3
// speedup vs baseline: 1.0901x; 1.0437x over previous
#include <cuda_runtime.h>
#include <cstdint>

// LIF spike recurrence over the last (time) axis.
//   u = TAU*u*(1-o_prev) + x_t;  o = (u > VTH) ? 1 : 0
// x: [16,128,512,32] fp32 -> 1,048,576 neurons x 32 contiguous timesteps.
//
// Round 3: persistent double-buffered pipeline. Phase 1 is cp.async.cg
// (global->smem direct, L1 bypass); each warp prefetches tile i+1 while
// computing/storing tile i, so ~4KB of reads per warp stay in flight
// continuously and DRAM duty cycle rises. Warp-autonomous (no block syncs),
// XOR-swizzled smem rows, streaming STG.

#define TAU 0.25f
#define VTH 0.5f

#define THREADS 128
#define WARPS 4
#define F4_PER_WARP 256                    // 32 neurons * 8 float4
#define F4_PER_BUF (WARPS * F4_PER_WARP)   // 1024 float4 = 16 KB
#define F4_PER_TILE F4_PER_BUF             // block tile = 128 neurons

__device__ __forceinline__ void cp_async16(uint32_t smem_addr, const void* gptr) {
    asm volatile("cp.async.cg.shared.global [%0], [%1], 16;\n"
                 :: "r"(smem_addr), "l"(gptr) : "memory");
}
__device__ __forceinline__ void cp_commit() {
    asm volatile("cp.async.commit_group;\n" ::: "memory");
}
template <int N>
__device__ __forceinline__ void cp_wait() {
    asm volatile("cp.async.wait_group %0;\n" :: "n"(N) : "memory");
}

__global__ __launch_bounds__(THREADS, 7)
void lif_kernel(const float4* __restrict__ x, float4* __restrict__ out,
                int ntiles) {
    __shared__ float4 buf[2][F4_PER_BUF];  // 32 KB total

    const int lane = threadIdx.x & 31;
    const int warp = threadIdx.x >> 5;

    // Per-lane prefetch of this warp's slice of a tile into buffer b.
    auto prefetch = [&](int tile, int b) {
        const size_t gbase = (size_t)tile * F4_PER_TILE + (size_t)warp * F4_PER_WARP;
        uint32_t sbase = (uint32_t)__cvta_generic_to_shared(
            &buf[b][warp * F4_PER_WARP]);
        #pragma unroll
        for (int i = 0; i < 8; i++) {
            int g = i * 32 + lane;
            int n = g >> 3;
            int j = g & 7;
            cp_async16(sbase + (((n << 3) | (j ^ (n & 7))) * 16u),
                       &x[gbase + g]);
        }
        cp_commit();
    };

    int tile = blockIdx.x;
    int b = 0;
    if (tile < ntiles) prefetch(tile, 0);

    for (; tile < ntiles; tile += gridDim.x) {
        const int next = tile + gridDim.x;
        if (next < ntiles) {
            prefetch(next, b ^ 1);
            cp_wait<1>();   // current tile's group done; next may be pending
        } else {
            cp_wait<0>();
        }
        __syncwarp();       // all lanes' copies visible warp-wide

        float4* wtile = &buf[b][warp * F4_PER_WARP];

        // Serial recurrence: lane owns neuron `lane`, swizzled smem row.
        {
            const int n = lane;
            float u = 0.0f, o = 0.0f;
            #pragma unroll
            for (int j = 0; j < 8; j++) {
                const int idx = (n << 3) | (j ^ (n & 7));
                float4 f = wtile[idx];

                u = TAU * u * (1.0f - o) + f.x;
                o = (u > VTH) ? 1.0f : 0.0f;
                f.x = o;

                u = TAU * u * (1.0f - o) + f.y;
                o = (u > VTH) ? 1.0f : 0.0f;
                f.y = o;

                u = TAU * u * (1.0f - o) + f.z;
                o = (u > VTH) ? 1.0f : 0.0f;
                f.z = o;

                u = TAU * u * (1.0f - o) + f.w;
                o = (u > VTH) ? 1.0f : 0.0f;
                f.w = o;

                wtile[idx] = f;
            }
        }
        __syncwarp();

        // Coalesced streaming store of the tile's spikes.
        {
            const size_t gbase = (size_t)tile * F4_PER_TILE + (size_t)warp * F4_PER_WARP;
            #pragma unroll
            for (int i = 0; i < 8; i++) {
                int g = i * 32 + lane;
                int n = g >> 3;
                int j = g & 7;
                __stcs(&out[gbase + g], wtile[(n << 3) | (j ^ (n & 7))]);
            }
        }
        __syncwarp();  // smem reads done before this buffer is re-prefetched

        b ^= 1;
    }
}

extern "C" void kernel_launch(void* const* d_in, const int* in_sizes, int n_in,
                              void* d_out, int out_size) {
    const float4* x = (const float4*)d_in[0];
    float4* o = (float4*)d_out;

    long long n_floats = in_sizes[0];          // 33,554,432
    long long neurons = n_floats / 32;         // 1,048,576
    int ntiles = (int)(neurons / (F4_PER_TILE / 8));   // 8192 tiles of 128 neurons

    int blocks = 1024;                         // persistent, 8 tiles each
    if (blocks > ntiles) blocks = ntiles;

    lif_kernel<<<blocks, THREADS>>>(x, o, ntiles);
}